// round 17
// baseline (speedup 1.0000x reference)
#include <cuda_runtime.h>
#include <cuda_fp16.h>
#include <cstdint>

// out[b,k] = sum_{i,j} x[b,i] W[k,i,j] x[b,j]
// Diagonal pair enumeration: k-step kk (0..8), slot c (0..15) -> pair (i=c, j=(c+kk)&15).
// GEMM per warp-tile: D[16 x 16] += A[16 x 144] * B[144 x 16] via mma.sync.m16n8k16 FP16.
// R17: A-fragment products computed in PACKED f16 (mul.rn.f16x2): x converted once
// per tile to 16 overlapping f16 pairs xp[m]={x[m],x[m+1]}; each kk is then just
// 4 HMUL2 + 2 HMMA (was 8 FMUL + 4 CVT + 2 HMMA). Error ~2 roundings (~4e-4 < 1e-3).
// Keeps: cp.async double buffer, stride-24 conflict-free gather, channel-permuted
// STG.128 epilogue, PDL prep overlap.

#define NKST 9
#define ITER 4
#define WARPS 4
#define ROWS_PER_BLOCK (WARPS * ITER * 16)  // 256
#define XSTRIDE 24                          // floats per sX row (conflict-free gather)

// B fragment table: [kk][lane] -> uint4 {B_nt0.x, B_nt0.y, B_nt1.x, B_nt1.y}
__device__ uint4 g_B[NKST * 32];

__device__ __forceinline__ float wd_val(const float* W, int d, int i, int n) {
    int j = (i + d) & 15;
    float v = W[n * 256 + i * 16 + j];
    if (d == 0) return v;
    if (d == 8 && i >= 8) return 0.0f;
    return v + W[n * 256 + j * 16 + i];
}

__device__ __forceinline__ uint32_t pack_f16_pair(float lo_elem, float hi_elem) {
    __half l = __float2half_rn(lo_elem);
    __half h = __float2half_rn(hi_elem);
    return (uint32_t)*(uint16_t*)&l | ((uint32_t)*(uint16_t*)&h << 16);
}

__global__ void prep_kernel(const float* __restrict__ W) {
    // allow the dependent main kernel to begin launching immediately;
    // its cudaGridDependencySynchronize() still waits for our completion.
    cudaTriggerProgrammaticLaunchCompletion();

    int id = blockIdx.x * blockDim.x + threadIdx.x;   // NKST*32 = 288
    if (id >= NKST * 32) return;
    int lane = id & 31;
    int kk = id >> 5;
    int gr = lane >> 2, tc = lane & 3;

#pragma unroll
    for (int nt = 0; nt < 2; ++nt) {
        // channel permutation: fragment nt, n-position gr -> output channel gr*2+nt
        int n = gr * 2 + nt;
        float w0 = wd_val(W, kk, tc * 2, n);
        float w1 = wd_val(W, kk, tc * 2 + 1, n);
        float w2 = wd_val(W, kk, tc * 2 + 8, n);
        float w3 = wd_val(W, kk, tc * 2 + 9, n);
        uint32_t pa = pack_f16_pair(w0, w1);
        uint32_t pb = pack_f16_pair(w2, w3);
        if (nt == 0) { g_B[id].x = pa; g_B[id].y = pb; }
        else         { g_B[id].z = pa; g_B[id].w = pb; }
    }
}

// pack two f32 -> f16x2 (low half = first arg)
__device__ __forceinline__ uint32_t f16pack(float lo_elem, float hi_elem) {
    uint32_t r;
    asm("cvt.rn.f16x2.f32 %0, %1, %2;" : "=r"(r) : "f"(hi_elem), "f"(lo_elem));
    return r;
}

__device__ __forceinline__ uint32_t hmul2(uint32_t a, uint32_t b) {
    uint32_t r;
    asm("mul.rn.f16x2 %0, %1, %2;" : "=r"(r) : "r"(a), "r"(b));
    return r;
}

// {a.hi_f16, b.lo_f16}: result lo = a bytes[3:2], hi = b bytes[1:0]
__device__ __forceinline__ uint32_t prmt5432(uint32_t a, uint32_t b) {
    uint32_t r;
    asm("prmt.b32 %0, %1, %2, 0x5432;" : "=r"(r) : "r"(a), "r"(b));
    return r;
}

__device__ __forceinline__ void hmma(float& d0, float& d1, float& d2, float& d3,
                                     uint32_t a0, uint32_t a1, uint32_t a2, uint32_t a3,
                                     uint32_t b0, uint32_t b1) {
    asm volatile(
        "mma.sync.aligned.m16n8k16.row.col.f32.f16.f16.f32 "
        "{%0,%1,%2,%3}, {%4,%5,%6,%7}, {%8,%9}, {%0,%1,%2,%3};"
        : "+f"(d0), "+f"(d1), "+f"(d2), "+f"(d3)
        : "r"(a0), "r"(a1), "r"(a2), "r"(a3), "r"(b0), "r"(b1));
}

__device__ __forceinline__ uint32_t smem_u32(const void* p) {
    uint32_t a;
    asm("{ .reg .u64 t; cvta.to.shared.u64 t, %1; cvt.u32.u64 %0, t; }" : "=r"(a) : "l"(p));
    return a;
}

__device__ __forceinline__ void cp16(uint32_t dst, const void* src) {
    asm volatile("cp.async.cg.shared.global [%0], [%1], 16;" :: "r"(dst), "l"(src) : "memory");
}

__global__ void __launch_bounds__(128, 5)
bilinear_hmma(const float* __restrict__ x, float* __restrict__ out) {
    __shared__ __align__(16) float sX[2][WARPS][16][XSTRIDE];  // double-buffered

    int tid = threadIdx.x;
    int wid = tid >> 5, lane = tid & 31;
    int gr = lane >> 2, tc = lane & 3;
    int i0 = tc * 2;

    // per-thread cp.async destination offsets (two 16B chunks)
    uint32_t dA0 = smem_u32(&sX[0][wid][lane >> 2][(lane & 3) * 4]);
    uint32_t dA1 = smem_u32(&sX[0][wid][(lane + 32) >> 2][(lane & 3) * 4]);
    const uint32_t BUFSTRIDE = (uint32_t)(WARPS * 16 * XSTRIDE * 4);  // bytes between buffers

    int tb0 = blockIdx.x * ROWS_PER_BLOCK + wid * (ITER * 16);

    // prologue: stage tile 0 into buffer 0 (independent of prep's output)
    {
        const float4* g = (const float4*)(x + (size_t)tb0 * 16);
        cp16(dA0, g + lane);
        cp16(dA1, g + lane + 32);
        asm volatile("cp.async.commit_group;" ::: "memory");
    }

    // PDL: wait for prep_kernel completion before touching g_B
    cudaGridDependencySynchronize();

    // B fragments -> registers (iteration-invariant; 9 broadcast LDG.128)
    uint4 Bv[NKST];
#pragma unroll
    for (int kk = 0; kk < NKST; ++kk)
        Bv[kk] = g_B[kk * 32 + lane];

#pragma unroll 1
    for (int it = 0; it < ITER; ++it) {
        int buf = it & 1;
        // issue next tile's copy into the other buffer (overlaps with compute)
        if (it + 1 < ITER) {
            const float4* g = (const float4*)(x + (size_t)(tb0 + (it + 1) * 16) * 16);
            uint32_t off = (uint32_t)((it + 1) & 1) * BUFSTRIDE;
            cp16(dA0 + off, g + lane);
            cp16(dA1 + off, g + lane + 32);
            asm volatile("cp.async.commit_group;" ::: "memory");
            asm volatile("cp.async.wait_group 1;" ::: "memory");
        } else {
            asm volatile("cp.async.wait_group 0;" ::: "memory");
        }
        __syncwarp();

        int tb = tb0 + it * 16;

        // gather + convert: xp[m] = f16x2 {x[(i0+m)&15], x[(i0+m+1)&15]} per row.
        // evens from the LDS.64 float2 directly; odds via PRMT of neighbors.
        uint32_t xp0[16], xp1[16];
#pragma unroll
        for (int m = 0; m < 16; m += 2) {
            int c = (i0 + m) & 15;
            float2 v0 = *(const float2*)&sX[buf][wid][gr][c];
            float2 v1 = *(const float2*)&sX[buf][wid][gr + 8][c];
            xp0[m] = f16pack(v0.x, v0.y);
            xp1[m] = f16pack(v1.x, v1.y);
        }
#pragma unroll
        for (int m = 1; m < 16; m += 2) {
            xp0[m] = prmt5432(xp0[m - 1], xp0[(m + 1) & 15]);
            xp1[m] = prmt5432(xp1[m - 1], xp1[(m + 1) & 15]);
        }

        // 2 independent HMMA chains (nt0 -> even channels, nt1 -> odd channels)
        float a0c[4] = {0.f, 0.f, 0.f, 0.f};
        float a1c[4] = {0.f, 0.f, 0.f, 0.f};

#pragma unroll
        for (int kk = 0; kk < NKST; ++kk) {
            // packed products: {x[c]*x[c+kk], x[c+1]*x[c+kk+1]} (all indices mod 16)
            uint32_t a0 = hmul2(xp0[0], xp0[kk]);
            uint32_t a1 = hmul2(xp1[0], xp1[kk]);
            uint32_t a2 = hmul2(xp0[8], xp0[(8 + kk) & 15]);
            uint32_t a3 = hmul2(xp1[8], xp1[(8 + kk) & 15]);

            hmma(a0c[0], a0c[1], a0c[2], a0c[3], a0, a1, a2, a3, Bv[kk].x, Bv[kk].y);
            hmma(a1c[0], a1c[1], a1c[2], a1c[3], a0, a1, a2, a3, Bv[kk].z, Bv[kk].w);
        }

        // epilogue: thread (gr,tc) owns channels 4tc..4tc+3 of rows gr, gr+8 -> STG.128
        {
            float4 v0 = make_float4(a0c[0], a1c[0], a0c[1], a1c[1]);
            float4 v1 = make_float4(a0c[2], a1c[2], a0c[3], a1c[3]);
            *(float4*)(out + (size_t)(tb + gr) * 16 + tc * 4)     = v0;
            *(float4*)(out + (size_t)(tb + gr + 8) * 16 + tc * 4) = v1;
        }
        // buffer it&1 is only rewritten at iteration it+1's issue point (SIMT lockstep)
    }
}

extern "C" void kernel_launch(void* const* d_in, const int* in_sizes, int n_in,
                              void* d_out, int out_size) {
    const float* x = (const float*)d_in[0];
    const float* W = (const float*)d_in[1];
    if (n_in >= 2 && in_sizes[0] == 4096) {  // defensive input identification
        W = (const float*)d_in[0];
        x = (const float*)d_in[1];
    }
    float* out = (float*)d_out;

    prep_kernel<<<2, 256>>>(W);  // 288 table entries

    const unsigned int B = 1048576u;

    // PDL launch: overlap main's prologue with prep's tail
    cudaLaunchConfig_t cfg = {};
    cfg.gridDim = dim3(B / ROWS_PER_BLOCK);
    cfg.blockDim = dim3(128);
    cfg.dynamicSmemBytes = 0;
    cudaLaunchAttribute attrs[1];
    attrs[0].id = cudaLaunchAttributeProgrammaticStreamSerialization;
    attrs[0].val.programmaticStreamSerializationAllowed = 1;
    cfg.attrs = attrs;
    cfg.numAttrs = 1;
    cudaError_t e = cudaLaunchKernelEx(&cfg, bilinear_hmma, x, out);
    if (e != cudaSuccess) {
        // fallback: plain serialized launch
        bilinear_hmma<<<B / ROWS_PER_BLOCK, 128>>>(x, out);
    }
}